// round 6
// baseline (speedup 1.0000x reference)
#include <cuda_runtime.h>
#include <cuda_fp16.h>
#include <mma.h>
#include <math.h>

using namespace nvcuda;

#define NN 100000
#define EE 800000
#define H  32
#define NL 4
#define FULL 0xffffffffu
#define SCAN_N   (NN + 1)
#define SCAN_NB  ((SCAN_N + 1023) / 1024)

// ---------------- scratch ---------------------------------------------------------
__device__ float  g_h[NN*H];
__device__ float  g_hnew[NN*H];
__device__ float  g_Ah[NN*H];
__device__ float  g_Bh[NN*H];
__device__ float  g_Uh[NN*H];
__device__ float  g_Vh[NN*H];
__device__ __half g_e[EE*H];       // e_l (dst-sorted)
__device__ __half g_enew[EE*H];    // enew_l (dst-sorted)
__device__ float  g_numden[2*NN*H];
// stats slots: per layer l: [l*128 + 0:64) h sum/sq, [l*128+64:128) e sum/sq
__device__ float  g_stats[NL*128];
__device__ int    g_hist[SCAN_NB*1024];
__device__ int    g_rowptr[NN+1];
__device__ int    g_cursor[NN];
__device__ int    g_bsum[SCAN_NB];
__device__ int    g_boff[SCAN_NB];
__device__ int    g_ssrc[EE];
__device__ int    g_sdst[EE];
__device__ int    g_oid[EE];

// ---------------- CSR build -------------------------------------------------------
__global__ void hist_kernel(const int* __restrict__ dst, int ne)
{
    for (int i = blockIdx.x * blockDim.x + threadIdx.x; i < ne;
         i += gridDim.x * blockDim.x)
        atomicAdd(&g_hist[dst[i]], 1);
}

__global__ void scanA()
{
    __shared__ int sm[1024];
    int idx = blockIdx.x * 1024 + threadIdx.x;
    int v = (idx < SCAN_N) ? g_hist[idx] : 0;
    sm[threadIdx.x] = v;
    __syncthreads();
    for (int off = 512; off > 0; off >>= 1) {
        if (threadIdx.x < off) sm[threadIdx.x] += sm[threadIdx.x + off];
        __syncthreads();
    }
    if (threadIdx.x == 0) g_bsum[blockIdx.x] = sm[0];
}

__global__ void scanB()
{
    __shared__ int sm[128];
    int t = threadIdx.x;
    sm[t] = (t < SCAN_NB) ? g_bsum[t] : 0;
    __syncthreads();
    for (int off = 1; off < 128; off <<= 1) {
        int v = (t >= off) ? sm[t - off] : 0;
        __syncthreads();
        sm[t] += v;
        __syncthreads();
    }
    if (t < SCAN_NB) g_boff[t] = sm[t] - g_bsum[t];
    // zero stats while we're here (runs before any layer kernel)
    for (int i = t; i < NL*128; i += 128) g_stats[i] = 0.f;
}

__global__ void scanC()
{
    __shared__ int sm[1024];
    int idx = blockIdx.x * 1024 + threadIdx.x;
    int t = threadIdx.x;
    int v = (idx < SCAN_N) ? g_hist[idx] : 0;
    sm[t] = v;
    __syncthreads();
    for (int off = 1; off < 1024; off <<= 1) {
        int u = (t >= off) ? sm[t - off] : 0;
        __syncthreads();
        sm[t] += u;
        __syncthreads();
    }
    if (idx < SCAN_N) {
        int excl = sm[t] - v + g_boff[blockIdx.x];
        g_rowptr[idx] = excl;
        if (idx < NN) g_cursor[idx] = excl;
    }
}

__global__ void scatter_kernel(const int* __restrict__ src, const int* __restrict__ dst,
                               int ne)
{
    for (int i = blockIdx.x * blockDim.x + threadIdx.x; i < ne;
         i += gridDim.x * blockDim.x) {
        int d = dst[i];
        int pos = atomicAdd(&g_cursor[d], 1);
        g_ssrc[pos] = src[i];
        g_sdst[pos] = d;
        g_oid[pos]  = i;
    }
}

// ---------------- input projections -----------------------------------------------
__global__ void proj_h(const float* __restrict__ x, const float* __restrict__ w,
                       const float* __restrict__ b, int n)
{
    int total = n * H;
    for (int t = blockIdx.x * blockDim.x + threadIdx.x; t < total;
         t += gridDim.x * blockDim.x) {
        int row = t >> 5, lane = t & 31;
        g_h[t] = x[row] * w[lane] + b[lane];
    }
}

__global__ void proj_e(const float* __restrict__ ein, const float* __restrict__ w,
                       const float* __restrict__ b, int ne)
{
    int total = ne * H;
    for (int t = blockIdx.x * blockDim.x + threadIdx.x; t < total;
         t += gridDim.x * blockDim.x) {
        int row = t >> 5, lane = t & 31;
        g_e[t] = __float2half_rn(ein[g_oid[row]] * w[lane] + b[lane]);
    }
}

// ------- gemm4, with h-update of previous layer fused (l>=1) ----------------------
__global__ void gemm4_fused(const float* __restrict__ Aw, const float* __restrict__ Ab,
                            const float* __restrict__ Bw, const float* __restrict__ Bb,
                            const float* __restrict__ Uw, const float* __restrict__ Ub,
                            const float* __restrict__ Vw, const float* __restrict__ Vb,
                            const float* __restrict__ bng, const float* __restrict__ bnb,
                            int statSlot, int applyUpd, int n)
{
    __shared__ float wA[H*H], wB[H*H], wU[H*H], wV[H*H];
    __shared__ float bA[H], bB[H], bU[H], bV[H];
    for (int i = threadIdx.x; i < H*H; i += blockDim.x) {
        wA[i] = Aw[i]; wB[i] = Bw[i]; wU[i] = Uw[i]; wV[i] = Vw[i];
    }
    if (threadIdx.x < H) {
        bA[threadIdx.x] = Ab[threadIdx.x];
        bB[threadIdx.x] = Bb[threadIdx.x];
        bU[threadIdx.x] = Ub[threadIdx.x];
        bV[threadIdx.x] = Vb[threadIdx.x];
    }
    __syncthreads();

    int lane = threadIdx.x & 31;
    float mn = 0.f, sc = 0.f, bt = 0.f;
    if (applyUpd) {
        float inv = 1.0f / (float)n;
        float s1 = g_stats[statSlot*128 + lane];
        float s2 = g_stats[statSlot*128 + 32 + lane];
        mn = s1 * inv;
        float var = s2 * inv - mn * mn;
        sc = rsqrtf(var + 1e-5f) * bng[lane];
        bt = bnb[lane];
    }

    int row = blockIdx.x * (blockDim.x >> 5) + (threadIdx.x >> 5);
    if (row >= n) return;
    float hv = g_h[row*H + lane];
    if (applyUpd) {
        float v = (g_hnew[row*H + lane] - mn) * sc + bt;
        hv += fmaxf(v, 0.f);
        g_h[row*H + lane] = hv;
    }
    float a = bA[lane], b = bB[lane], u = bU[lane], v = bV[lane];
    #pragma unroll
    for (int k = 0; k < H; k++) {
        float hk = __shfl_sync(FULL, hv, k);
        a += hk * wA[k*H + lane];
        b += hk * wB[k*H + lane];
        u += hk * wU[k*H + lane];
        v += hk * wV[k*H + lane];
    }
    g_Ah[row*H + lane] = a;
    g_Bh[row*H + lane] = b;
    g_Uh[row*H + lane] = u;
    g_Vh[row*H + lane] = v;
}

// ===== edge megakernel ==============================================================
// Per 16-row tile (1 warp): apply prev-layer e-BN update, tensor-core GEMM with W
// (fp32 weights, hi/lo fp16 split), then:
//   mode 0: enew = Ah[dst]+Bh[src]+ce; write enew; e-stats; sigmoid; segmented
//           num/den accumulation with per-dst atomic flush (rows are dst-sorted).
//   mode 1: hid = relu(Ah2[src]+Bh2[dst]+ce); out[oid] = hid . W2 + b2.
__global__ void edge_mega(const float* __restrict__ W, const float* __restrict__ bias,
                          const float* __restrict__ bng, const float* __restrict__ bnb,
                          int prevSlot, int curSlot, int applyUpd, int mode,
                          const float* __restrict__ W2, const float* __restrict__ b2,
                          float* __restrict__ out, int ne, float inv_ne)
{
    __shared__ __half sWhi[32*32], sWlo[32*32];
    __shared__ __half sE[4][16*32];
    __shared__ float  sC[4][16*32];
    __shared__ float  sBias[32], sMn[32], sSc[32], sBt[32];
    __shared__ float  sSum[32], sSq[32];

    int tid = threadIdx.x;
    for (int i = tid; i < 1024; i += 128) {
        float w = W[i];
        __half hi = __float2half_rn(w);
        sWhi[i] = hi;
        sWlo[i] = __float2half_rn(w - __half2float(hi));
    }
    if (tid < 32) {
        sBias[tid] = bias ? bias[tid] : 0.f;
        sSum[tid] = 0.f; sSq[tid] = 0.f;
        if (applyUpd) {
            float s1 = g_stats[prevSlot*128 + 64 + tid];
            float s2 = g_stats[prevSlot*128 + 96 + tid];
            float mean = s1 * inv_ne;
            float var  = s2 * inv_ne - mean * mean;
            sMn[tid] = mean;
            sSc[tid] = rsqrtf(var + 1e-5f) * bng[tid];
            sBt[tid] = bnb[tid];
        } else { sMn[tid] = 0.f; sSc[tid] = 0.f; sBt[tid] = 0.f; }
    }
    __syncthreads();

    int warp = tid >> 5, lane = tid & 31;
    float* g_num = g_numden;
    float* g_den = g_numden + (size_t)NN*H;

    wmma::fragment<wmma::matrix_b, 16,16,16, __half, wmma::row_major> bh[2][2], bl[2][2];
    #pragma unroll
    for (int kk = 0; kk < 2; kk++)
        #pragma unroll
        for (int nn = 0; nn < 2; nn++) {
            wmma::load_matrix_sync(bh[kk][nn], sWhi + kk*16*32 + nn*16, 32);
            wmma::load_matrix_sync(bl[kk][nn], sWlo + kk*16*32 + nn*16, 32);
        }

    __half2* e2 = (__half2*)g_e;
    const __half2* en2 = (const __half2*)g_enew;
    float w2 = 0.f, bb2 = 0.f;
    if (mode == 1) { w2 = W2[lane]; bb2 = b2[0]; }

    float ls = 0.f, lq = 0.f;
    int ntiles = (ne + 63) >> 6;

    for (int t = blockIdx.x; t < ntiles; t += gridDim.x) {
        int rbase = t*64 + warp*16;
        __half2* stage = (__half2*)sE[warp];
        // stage updated e tile (16 rows x 16 half2)
        #pragma unroll
        for (int i = 0; i < 8; i++) {
            int idx = i*32 + lane;
            int row = rbase + (idx >> 4);
            int ch  = idx & 15;
            if (row < ne) {
                size_t g = (size_t)row*16 + ch;
                __half2 ev = e2[g];
                if (applyUpd) {
                    float2 f  = __half22float2(ev);
                    float2 en = __half22float2(en2[g]);
                    int c = ch*2;
                    f.x += fmaxf((en.x - sMn[c])   * sSc[c]   + sBt[c],   0.f);
                    f.y += fmaxf((en.y - sMn[c+1]) * sSc[c+1] + sBt[c+1], 0.f);
                    __half2 nv = __floats2half2_rn(f.x, f.y);
                    if (mode == 0) e2[g] = nv;   // next layer reads e; score pass doesn't
                    stage[idx] = nv;
                } else {
                    stage[idx] = ev;
                }
            } else {
                stage[idx] = __floats2half2_rn(0.f, 0.f);
            }
        }
        __syncwarp();

        wmma::fragment<wmma::matrix_a, 16,16,16, __half, wmma::row_major> a0, a1;
        wmma::load_matrix_sync(a0, sE[warp],      32);
        wmma::load_matrix_sync(a1, sE[warp] + 16, 32);

        wmma::fragment<wmma::accumulator, 16,16,16, float> acc0, acc1;
        wmma::fill_fragment(acc0, 0.f);
        wmma::fill_fragment(acc1, 0.f);
        wmma::mma_sync(acc0, a0, bh[0][0], acc0);
        wmma::mma_sync(acc0, a1, bh[1][0], acc0);
        wmma::mma_sync(acc0, a0, bl[0][0], acc0);
        wmma::mma_sync(acc0, a1, bl[1][0], acc0);
        wmma::mma_sync(acc1, a0, bh[0][1], acc1);
        wmma::mma_sync(acc1, a1, bh[1][1], acc1);
        wmma::mma_sync(acc1, a0, bl[0][1], acc1);
        wmma::mma_sync(acc1, a1, bl[1][1], acc1);

        wmma::store_matrix_sync(sC[warp],      acc0, 32, wmma::mem_row_major);
        wmma::store_matrix_sync(sC[warp] + 16, acc1, 32, wmma::mem_row_major);
        __syncwarp();

        if (mode == 0) {
            int prev_d = -1;
            float num = 0.f, den = 0.f;
            #pragma unroll 4
            for (int r = 0; r < 16; r++) {
                int row = rbase + r;
                if (row >= ne) break;
                int s = g_ssrc[row], d = g_sdst[row];
                float ce  = sC[warp][r*32 + lane] + sBias[lane];
                float enw = g_Ah[d*H + lane] + g_Bh[s*H + lane] + ce;
                g_enew[(size_t)row*H + lane] = __float2half_rn(enw);
                ls += enw; lq += enw * enw;
                float sig = 1.0f / (1.0f + __expf(-enw));
                if (d != prev_d) {
                    if (prev_d >= 0) {
                        atomicAdd(&g_num[prev_d*H + lane], num);
                        atomicAdd(&g_den[prev_d*H + lane], den);
                    }
                    num = 0.f; den = 0.f;
                    prev_d = d;
                }
                num += sig * g_Vh[s*H + lane];
                den += sig;
            }
            if (prev_d >= 0) {
                atomicAdd(&g_num[prev_d*H + lane], num);
                atomicAdd(&g_den[prev_d*H + lane], den);
            }
        } else {
            #pragma unroll 4
            for (int r = 0; r < 16; r++) {
                int row = rbase + r;
                if (row >= ne) break;
                int s = g_ssrc[row], d = g_sdst[row];
                float ce  = sC[warp][r*32 + lane];
                float hid = g_Ah[s*H + lane] + g_Bh[d*H + lane] + ce;
                hid = fmaxf(hid, 0.f);
                float p = hid * w2;
                #pragma unroll
                for (int off = 16; off > 0; off >>= 1)
                    p += __shfl_xor_sync(FULL, p, off);
                if (lane == 0) out[g_oid[row]] = p + bb2;
            }
        }
        __syncwarp();
    }

    if (mode == 0) {
        atomicAdd(&sSum[lane], ls);
        atomicAdd(&sSq[lane],  lq);
        __syncthreads();
        if (tid < 32) {
            atomicAdd(&g_stats[curSlot*128 + 64 + tid], sSum[tid]);
            atomicAdd(&g_stats[curSlot*128 + 96 + tid], sSq[tid]);
        }
    }
}

// ---- node finalize: hnew = Uh + num/(den+eps); h-stats ---------------------------
__global__ void node_fin(int curSlot, int n)
{
    __shared__ float sSum[32], sSq[32];
    if (threadIdx.x < 32) { sSum[threadIdx.x] = 0.f; sSq[threadIdx.x] = 0.f; }
    __syncthreads();

    const float* g_num = g_numden;
    const float* g_den = g_numden + (size_t)NN*H;
    int lane = threadIdx.x & 31;
    float hs = 0.f, hq = 0.f;
    int total = n * H;
    for (int t = blockIdx.x * blockDim.x + threadIdx.x; t < total;
         t += gridDim.x * blockDim.x) {
        float v = g_Uh[t] + g_num[t] / (g_den[t] + 1e-6f);
        g_hnew[t] = v;
        hs += v; hq += v * v;
    }
    atomicAdd(&sSum[lane], hs);
    atomicAdd(&sSq[lane],  hq);
    __syncthreads();
    if (threadIdx.x < 32) {
        atomicAdd(&g_stats[curSlot*128 + threadIdx.x],      sSum[threadIdx.x]);
        atomicAdd(&g_stats[curSlot*128 + 32 + threadIdx.x], sSq[threadIdx.x]);
    }
}

// ---- score pre-pass: final h-update fused; hid_src -> g_Ah, hid_dst -> g_Bh ------
__global__ void score_gemm2(const float* __restrict__ W1, const float* __restrict__ b1,
                            const float* __restrict__ bng, const float* __restrict__ bnb,
                            int statSlot, int n)
{
    int lane = threadIdx.x & 31;
    float ws[32], wd[32];
    #pragma unroll
    for (int k = 0; k < 32; k++) {
        ws[k] = W1[k*32 + lane];
        wd[k] = W1[(32 + k)*32 + lane];
    }
    float bb = b1[lane];
    float inv = 1.0f / (float)n;
    float s1 = g_stats[statSlot*128 + lane];
    float s2 = g_stats[statSlot*128 + 32 + lane];
    float mn = s1 * inv;
    float var = s2 * inv - mn * mn;
    float sc = rsqrtf(var + 1e-5f) * bng[lane];
    float bt = bnb[lane];

    int row = blockIdx.x * (blockDim.x >> 5) + (threadIdx.x >> 5);
    if (row >= n) return;
    float hv = g_h[row*H + lane];
    hv += fmaxf((g_hnew[row*H + lane] - mn) * sc + bt, 0.f);
    float a = bb, c = 0.f;
    #pragma unroll
    for (int k = 0; k < 32; k++) {
        float hk = __shfl_sync(FULL, hv, k);
        a += hk * ws[k];
        c += hk * wd[k];
    }
    g_Ah[row*H + lane] = a;
    g_Bh[row*H + lane] = c;
}

// ==================================================================================
extern "C" void kernel_launch(void* const* d_in, const int* in_sizes, int n_in,
                              void* d_out, int out_size)
{
    const float* x    = (const float*)d_in[0];
    const float* ein  = (const float*)d_in[1];
    const int*   eidx = (const int*)  d_in[2];
    const float* pe_w = (const float*)d_in[3];
    const float* pe_b = (const float*)d_in[4];
    const float* ed_w = (const float*)d_in[5];
    const float* ed_b = (const float*)d_in[6];
    const float* A_w  = (const float*)d_in[7];
    const float* A_b  = (const float*)d_in[8];
    const float* B_w  = (const float*)d_in[9];
    const float* B_b  = (const float*)d_in[10];
    const float* C_w  = (const float*)d_in[11];
    const float* C_b  = (const float*)d_in[12];
    const float* U_w  = (const float*)d_in[13];
    const float* U_b  = (const float*)d_in[14];
    const float* V_w  = (const float*)d_in[15];
    const float* V_b  = (const float*)d_in[16];
    const float* bnhg = (const float*)d_in[17];
    const float* bnhb = (const float*)d_in[18];
    const float* bneg = (const float*)d_in[19];
    const float* bneb = (const float*)d_in[20];
    const float* W1_w = (const float*)d_in[21];
    const float* W1_b = (const float*)d_in[22];
    const float* W2_w = (const float*)d_in[23];
    const float* W2_b = (const float*)d_in[24];
    float* out = (float*)d_out;

    const int n  = in_sizes[0];
    const int ne = in_sizes[1];
    const int* src = eidx;
    const int* dst = eidx + ne;
    const float inv_ne = 1.0f / (float)ne;

    void *p_hist, *p_numden;
    cudaGetSymbolAddress(&p_hist,   g_hist);
    cudaGetSymbolAddress(&p_numden, g_numden);

    const int TB = 256;
    const int WPB = TB / 32;
    const int G_NODE_W = (n + WPB - 1) / WPB;
    const int G_MMA = 1480;

    // ---- CSR build (dst-sorted edge order); scanB also zeros g_stats ----
    cudaMemsetAsync(p_hist, 0, SCAN_NB * 1024 * sizeof(int));
    hist_kernel<<<800, TB>>>(dst, ne);
    scanA<<<SCAN_NB, 1024>>>();
    scanB<<<1, 128>>>();
    scanC<<<SCAN_NB, 1024>>>();
    scatter_kernel<<<800, TB>>>(src, dst, ne);

    // ---- input projections ----
    proj_h<<<1024, TB>>>(x, pe_w, pe_b, n);
    proj_e<<<4096, TB>>>(ein, ed_w, ed_b, ne);

    for (int l = 0; l < NL; l++) {
        cudaMemsetAsync(p_numden, 0, 2 * (size_t)n * H * sizeof(float));

        gemm4_fused<<<G_NODE_W, TB>>>(A_w + l*H*H, A_b + l*H,
                                      B_w + l*H*H, B_b + l*H,
                                      U_w + l*H*H, U_b + l*H,
                                      V_w + l*H*H, V_b + l*H,
                                      bnhg + (l-1)*H, bnhb + (l-1)*H,
                                      l-1, l > 0 ? 1 : 0, n);

        edge_mega<<<G_MMA, 128>>>(C_w + l*H*H, C_b + l*H,
                                  bneg + (l-1)*H, bneb + (l-1)*H,
                                  l-1, l, l > 0 ? 1 : 0, /*mode=*/0,
                                  (const float*)nullptr, (const float*)nullptr,
                                  (float*)nullptr, ne, inv_ne);

        node_fin<<<1024, TB>>>(l, n);
    }

    score_gemm2<<<G_NODE_W, TB>>>(W1_w, W1_b,
                                  bnhg + (NL-1)*H, bnhb + (NL-1)*H, NL-1, n);
    // final edge term: e BN update + W1[64:96] mma + hid + dot(W2) -> out
    edge_mega<<<G_MMA, 128>>>(W1_w + 64*32, (const float*)nullptr,
                              bneg + (NL-1)*H, bneb + (NL-1)*H,
                              NL-1, NL-1, /*applyUpd=*/1, /*mode=*/1,
                              W2_w, W2_b, out, ne, inv_ne);
}

// round 7
// speedup vs baseline: 1.2342x; 1.2342x over previous
#include <cuda_runtime.h>
#include <cuda_fp16.h>
#include <mma.h>
#include <math.h>

using namespace nvcuda;

#define NN 100000
#define EE 800000
#define H  32
#define NL 4
#define FULL 0xffffffffu
#define SCAN_N   (NN + 1)
#define SCAN_NB  ((SCAN_N + 1023) / 1024)

// ---------------- scratch ---------------------------------------------------------
__device__ float  g_h[NN*H];
__device__ float  g_hnew[NN*H];
__device__ float  g_Ah[NN*H];
__device__ float  g_Bh[NN*H];
__device__ float  g_Uh[NN*H];
__device__ float  g_Vh[NN*H];
__device__ __half g_e[EE*H];       // e_l (dst-sorted)
__device__ __half g_enew[EE*H];    // enew_l (dst-sorted)
__device__ __half g_ce[EE*H];      // Ce (fp16 storage, fp32 accum)
// stats slots: per layer l: [l*128 + 0:64) h sum/sq, [l*128+64:128) e sum/sq
__device__ float  g_stats[NL*128];
__device__ int    g_hist[SCAN_NB*1024];   // zero at load; scan re-zeros (leave-clean)
__device__ int    g_rowptr[NN+1];
__device__ int    g_cursor[NN];
__device__ int    g_bsum[SCAN_NB];
__device__ int    g_sync;
__device__ int    g_ssrc[EE];
__device__ int    g_sdst[EE];
__device__ int    g_oid[EE];

// ---------------- CSR build -------------------------------------------------------
// hist also resets g_sync and zeroes g_stats (runs before scan / any layer kernel)
__global__ void hist_kernel(const int* __restrict__ dst, int ne)
{
    if (blockIdx.x == 0) {
        if (threadIdx.x == 0) g_sync = 0;
        for (int i = threadIdx.x; i < NL*128; i += blockDim.x) g_stats[i] = 0.f;
    }
    for (int i = blockIdx.x * blockDim.x + threadIdx.x; i < ne;
         i += gridDim.x * blockDim.x)
        atomicAdd(&g_hist[dst[i]], 1);
}

// single-kernel scan: all SCAN_NB (=98) blocks resident; aggregate + spin barrier.
__global__ void scan_fused()
{
    __shared__ int sm[1024];
    int b = blockIdx.x, t = threadIdx.x;
    int idx = b*1024 + t;
    int v = (idx < SCAN_N) ? g_hist[idx] : 0;
    if (idx < SCAN_N) g_hist[idx] = 0;        // leave clean for next graph replay
    sm[t] = v;
    __syncthreads();
    for (int off = 1; off < 1024; off <<= 1) {
        int u = (t >= off) ? sm[t - off] : 0;
        __syncthreads();
        sm[t] += u;
        __syncthreads();
    }
    if (t == 1023) {
        g_bsum[b] = sm[1023];
        __threadfence();
        atomicAdd(&g_sync, 1);
    }
    if (t == 0) {
        while (atomicAdd(&g_sync, 0) < (int)gridDim.x) __nanosleep(64);
    }
    __syncthreads();
    int pre = 0;
    for (int i = 0; i < b; i++) pre += g_bsum[i];
    int excl = pre + sm[t] - v;
    if (idx < SCAN_N) {
        g_rowptr[idx] = excl;
        if (idx < NN) g_cursor[idx] = excl;
    }
}

__global__ void scatter_kernel(const int* __restrict__ src, const int* __restrict__ dst,
                               int ne)
{
    for (int i = blockIdx.x * blockDim.x + threadIdx.x; i < ne;
         i += gridDim.x * blockDim.x) {
        int d = dst[i];
        int pos = atomicAdd(&g_cursor[d], 1);
        g_ssrc[pos] = src[i];
        g_sdst[pos] = d;
        g_oid[pos]  = i;
    }
}

// ------- gemm4; l==0 computes h = x*pe_w+pe_b inline; l>=1 applies h-update -------
__global__ void gemm4_fused(const float* __restrict__ Aw, const float* __restrict__ Ab,
                            const float* __restrict__ Bw, const float* __restrict__ Bb,
                            const float* __restrict__ Uw, const float* __restrict__ Ub,
                            const float* __restrict__ Vw, const float* __restrict__ Vb,
                            const float* __restrict__ bng, const float* __restrict__ bnb,
                            const float* __restrict__ x,
                            const float* __restrict__ pw, const float* __restrict__ pb,
                            int statSlot, int mode /*0=proj,1=update*/, int n)
{
    __shared__ float wA[H*H], wB[H*H], wU[H*H], wV[H*H];
    __shared__ float bA[H], bB[H], bU[H], bV[H];
    for (int i = threadIdx.x; i < H*H; i += blockDim.x) {
        wA[i] = Aw[i]; wB[i] = Bw[i]; wU[i] = Uw[i]; wV[i] = Vw[i];
    }
    if (threadIdx.x < H) {
        bA[threadIdx.x] = Ab[threadIdx.x];
        bB[threadIdx.x] = Bb[threadIdx.x];
        bU[threadIdx.x] = Ub[threadIdx.x];
        bV[threadIdx.x] = Vb[threadIdx.x];
    }
    __syncthreads();

    int lane = threadIdx.x & 31;
    float mn = 0.f, sc = 0.f, bt = 0.f, pwl = 0.f, pbl = 0.f;
    if (mode == 1) {
        float inv = 1.0f / (float)n;
        float s1 = g_stats[statSlot*128 + lane];
        float s2 = g_stats[statSlot*128 + 32 + lane];
        mn = s1 * inv;
        float var = s2 * inv - mn * mn;
        sc = rsqrtf(var + 1e-5f) * bng[lane];
        bt = bnb[lane];
    } else {
        pwl = pw[lane]; pbl = pb[lane];
    }

    int row = blockIdx.x * (blockDim.x >> 5) + (threadIdx.x >> 5);
    if (row >= n) return;
    float hv;
    if (mode == 0) {
        hv = x[row] * pwl + pbl;
        g_h[row*H + lane] = hv;
    } else {
        hv = g_h[row*H + lane];
        float v = (g_hnew[row*H + lane] - mn) * sc + bt;
        hv += fmaxf(v, 0.f);
        g_h[row*H + lane] = hv;
    }
    float a = bA[lane], b = bB[lane], u = bU[lane], v = bV[lane];
    #pragma unroll
    for (int k = 0; k < H; k++) {
        float hk = __shfl_sync(FULL, hv, k);
        a += hk * wA[k*H + lane];
        b += hk * wB[k*H + lane];
        u += hk * wU[k*H + lane];
        v += hk * wV[k*H + lane];
    }
    g_Ah[row*H + lane] = a;
    g_Bh[row*H + lane] = b;
    g_Uh[row*H + lane] = u;
    g_Vh[row*H + lane] = v;
}

// ---- tensor-core edge GEMM -> fp16 ce. eMode: 0=read e as-is, 1=project e from
// ---- input (layer 0), 2=apply prev-layer BN update (write back iff writeE). ------
__global__ void ce_mma(const float* __restrict__ W, const float* __restrict__ bias,
                       const float* __restrict__ bng, const float* __restrict__ bnb,
                       const float* __restrict__ ein,
                       const float* __restrict__ ew, const float* __restrict__ eb,
                       int prevSlot, int eMode, int writeE, int ne, float inv_ne)
{
    __shared__ __half sWhi[32*32], sWlo[32*32];
    __shared__ __half sE[4][16*32];
    __shared__ float  sC[4][16*32];
    __shared__ float  sBias[32], sMn[32], sSc[32], sBt[32], sEw[32], sEb[32];

    int tid = threadIdx.x;
    for (int i = tid; i < 1024; i += 128) {
        float w = W[i];
        __half hi = __float2half_rn(w);
        sWhi[i] = hi;
        sWlo[i] = __float2half_rn(w - __half2float(hi));
    }
    if (tid < 32) {
        sBias[tid] = bias ? bias[tid] : 0.f;
        sMn[tid] = 0.f; sSc[tid] = 0.f; sBt[tid] = 0.f;
        sEw[tid] = 0.f; sEb[tid] = 0.f;
        if (eMode == 2) {
            float s1 = g_stats[prevSlot*128 + 64 + tid];
            float s2 = g_stats[prevSlot*128 + 96 + tid];
            float mean = s1 * inv_ne;
            float var  = s2 * inv_ne - mean * mean;
            sMn[tid] = mean;
            sSc[tid] = rsqrtf(var + 1e-5f) * bng[tid];
            sBt[tid] = bnb[tid];
        } else if (eMode == 1) {
            sEw[tid] = ew[tid]; sEb[tid] = eb[tid];
        }
    }
    __syncthreads();

    int warp = tid >> 5, lane = tid & 31;

    wmma::fragment<wmma::matrix_b, 16,16,16, __half, wmma::row_major> bh[2][2], bl[2][2];
    #pragma unroll
    for (int kk = 0; kk < 2; kk++)
        #pragma unroll
        for (int nn = 0; nn < 2; nn++) {
            wmma::load_matrix_sync(bh[kk][nn], sWhi + kk*16*32 + nn*16, 32);
            wmma::load_matrix_sync(bl[kk][nn], sWlo + kk*16*32 + nn*16, 32);
        }

    __half2* e2 = (__half2*)g_e;
    const __half2* en2 = (const __half2*)g_enew;
    int ntiles = (ne + 63) >> 6;

    for (int t = blockIdx.x; t < ntiles; t += gridDim.x) {
        int rbase = t*64 + warp*16;
        __half2* stage = (__half2*)sE[warp];
        #pragma unroll
        for (int i = 0; i < 8; i++) {
            int idx = i*32 + lane;
            int row = rbase + (idx >> 4);
            int ch  = idx & 15;
            if (row < ne) {
                size_t g = (size_t)row*16 + ch;
                if (eMode == 1) {
                    float xin = ein[g_oid[row]];
                    int c = ch*2;
                    __half2 nv = __floats2half2_rn(xin*sEw[c] + sEb[c],
                                                   xin*sEw[c+1] + sEb[c+1]);
                    e2[g] = nv;
                    stage[idx] = nv;
                } else if (eMode == 2) {
                    float2 f  = __half22float2(e2[g]);
                    float2 en = __half22float2(en2[g]);
                    int c = ch*2;
                    f.x += fmaxf((en.x - sMn[c])   * sSc[c]   + sBt[c],   0.f);
                    f.y += fmaxf((en.y - sMn[c+1]) * sSc[c+1] + sBt[c+1], 0.f);
                    __half2 nv = __floats2half2_rn(f.x, f.y);
                    if (writeE) e2[g] = nv;
                    stage[idx] = nv;
                } else {
                    stage[idx] = e2[g];
                }
            } else {
                stage[idx] = __floats2half2_rn(0.f, 0.f);
            }
        }
        __syncwarp();

        wmma::fragment<wmma::matrix_a, 16,16,16, __half, wmma::row_major> a0, a1;
        wmma::load_matrix_sync(a0, sE[warp],      32);
        wmma::load_matrix_sync(a1, sE[warp] + 16, 32);

        wmma::fragment<wmma::accumulator, 16,16,16, float> acc0, acc1;
        wmma::fill_fragment(acc0, 0.f);
        wmma::fill_fragment(acc1, 0.f);
        wmma::mma_sync(acc0, a0, bh[0][0], acc0);
        wmma::mma_sync(acc0, a1, bh[1][0], acc0);
        wmma::mma_sync(acc0, a0, bl[0][0], acc0);
        wmma::mma_sync(acc0, a1, bl[1][0], acc0);
        wmma::mma_sync(acc1, a0, bh[0][1], acc1);
        wmma::mma_sync(acc1, a1, bh[1][1], acc1);
        wmma::mma_sync(acc1, a0, bl[0][1], acc1);
        wmma::mma_sync(acc1, a1, bl[1][1], acc1);

        wmma::store_matrix_sync(sC[warp],      acc0, 32, wmma::mem_row_major);
        wmma::store_matrix_sync(sC[warp] + 16, acc1, 32, wmma::mem_row_major);
        __syncwarp();

        #pragma unroll
        for (int r = 0; r < 16; r++) {
            int row = rbase + r;
            if (row < ne)
                g_ce[(size_t)row*32 + lane] =
                    __float2half_rn(sC[warp][r*32 + lane] + sBias[lane]);
        }
        __syncwarp();
    }
}

// ---- aggregation: warp per node; ce precomputed; 4-edge ILP; no global atomics ---
__global__ void agg2(int curSlot, int n)
{
    int lane = threadIdx.x & 31;

    __shared__ float sE[32], qE[32], sH[32], qH[32];
    if (threadIdx.x < 32) {
        sE[threadIdx.x] = 0.f; qE[threadIdx.x] = 0.f;
        sH[threadIdx.x] = 0.f; qH[threadIdx.x] = 0.f;
    }
    __syncthreads();

    float ls = 0.f, lq = 0.f, hs = 0.f, hq = 0.f;
    int d = blockIdx.x * (blockDim.x >> 5) + (threadIdx.x >> 5);
    if (d < n) {
        int beg = g_rowptr[d], end = g_rowptr[d+1];
        float ah = g_Ah[d*H + lane];
        float uh = g_Uh[d*H + lane];
        float num = 0.f, den = 0.f;
        int i = beg;
        for (; i + 3 < end; i += 4) {
            int   s[4];
            float ce[4], bh[4], vh[4], en[4];
            #pragma unroll
            for (int j = 0; j < 4; j++) s[j] = g_ssrc[i+j];
            #pragma unroll
            for (int j = 0; j < 4; j++) ce[j] = __half2float(g_ce[(size_t)(i+j)*H + lane]);
            #pragma unroll
            for (int j = 0; j < 4; j++) bh[j] = g_Bh[s[j]*H + lane];
            #pragma unroll
            for (int j = 0; j < 4; j++) vh[j] = g_Vh[s[j]*H + lane];
            #pragma unroll
            for (int j = 0; j < 4; j++) {
                en[j] = ah + bh[j] + ce[j];
                g_enew[(size_t)(i+j)*H + lane] = __float2half_rn(en[j]);
                ls += en[j]; lq += en[j] * en[j];
                float sg = 1.0f / (1.0f + __expf(-en[j]));
                num += sg * vh[j];
                den += sg;
            }
        }
        for (; i < end; i++) {
            int s0 = g_ssrc[i];
            float e0 = ah + g_Bh[s0*H + lane] + __half2float(g_ce[(size_t)i*H + lane]);
            g_enew[(size_t)i*H + lane] = __float2half_rn(e0);
            ls += e0; lq += e0 * e0;
            float sg0 = 1.0f / (1.0f + __expf(-e0));
            num += sg0 * g_Vh[s0*H + lane];
            den += sg0;
        }
        float hn = uh + num / (den + 1e-6f);
        g_hnew[d*H + lane] = hn;
        hs += hn; hq += hn * hn;
    }
    atomicAdd(&sH[lane], hs); atomicAdd(&qH[lane], hq);
    atomicAdd(&sE[lane], ls); atomicAdd(&qE[lane], lq);
    __syncthreads();
    if (threadIdx.x < 32) {
        atomicAdd(&g_stats[curSlot*128 + threadIdx.x],      sH[threadIdx.x]);
        atomicAdd(&g_stats[curSlot*128 + 32 + threadIdx.x], qH[threadIdx.x]);
        atomicAdd(&g_stats[curSlot*128 + 64 + threadIdx.x], sE[threadIdx.x]);
        atomicAdd(&g_stats[curSlot*128 + 96 + threadIdx.x], qE[threadIdx.x]);
    }
}

// ---- score pre-pass: final h-update fused; hid_src -> g_Ah, hid_dst -> g_Bh ------
__global__ void score_gemm2(const float* __restrict__ W1, const float* __restrict__ b1,
                            const float* __restrict__ bng, const float* __restrict__ bnb,
                            int statSlot, int n)
{
    int lane = threadIdx.x & 31;
    float ws[32], wd[32];
    #pragma unroll
    for (int k = 0; k < 32; k++) {
        ws[k] = W1[k*32 + lane];
        wd[k] = W1[(32 + k)*32 + lane];
    }
    float bb = b1[lane];
    float inv = 1.0f / (float)n;
    float s1 = g_stats[statSlot*128 + lane];
    float s2 = g_stats[statSlot*128 + 32 + lane];
    float mn = s1 * inv;
    float var = s2 * inv - mn * mn;
    float sc = rsqrtf(var + 1e-5f) * bng[lane];
    float bt = bnb[lane];

    int row = blockIdx.x * (blockDim.x >> 5) + (threadIdx.x >> 5);
    if (row >= n) return;
    float hv = g_h[row*H + lane];
    hv += fmaxf((g_hnew[row*H + lane] - mn) * sc + bt, 0.f);
    float a = bb, c = 0.f;
    #pragma unroll
    for (int k = 0; k < 32; k++) {
        float hk = __shfl_sync(FULL, hv, k);
        a += hk * ws[k];
        c += hk * wd[k];
    }
    g_Ah[row*H + lane] = a;
    g_Bh[row*H + lane] = c;
}

// ---- score: hid = relu(hid_s + hid_d + hid_e); out = hid @ W2 + b2 ---------------
__global__ void score_final(const float* __restrict__ W2, const float* __restrict__ b2,
                            float* __restrict__ out, int ne)
{
    int lane = threadIdx.x & 31;
    float w2 = W2[lane];
    float bb2 = b2[0];

    int i = blockIdx.x * (blockDim.x >> 5) + (threadIdx.x >> 5);
    if (i >= ne) return;
    int s = g_ssrc[i], d = g_sdst[i], o = g_oid[i];
    float hid = g_Ah[s*H + lane] + g_Bh[d*H + lane]
              + __half2float(g_ce[(size_t)i*H + lane]);
    hid = fmaxf(hid, 0.f);
    float p = hid * w2;
    #pragma unroll
    for (int off = 16; off > 0; off >>= 1)
        p += __shfl_xor_sync(FULL, p, off);
    if (lane == 0) out[o] = p + bb2;
}

// ==================================================================================
extern "C" void kernel_launch(void* const* d_in, const int* in_sizes, int n_in,
                              void* d_out, int out_size)
{
    const float* x    = (const float*)d_in[0];
    const float* ein  = (const float*)d_in[1];
    const int*   eidx = (const int*)  d_in[2];
    const float* pe_w = (const float*)d_in[3];
    const float* pe_b = (const float*)d_in[4];
    const float* ed_w = (const float*)d_in[5];
    const float* ed_b = (const float*)d_in[6];
    const float* A_w  = (const float*)d_in[7];
    const float* A_b  = (const float*)d_in[8];
    const float* B_w  = (const float*)d_in[9];
    const float* B_b  = (const float*)d_in[10];
    const float* C_w  = (const float*)d_in[11];
    const float* C_b  = (const float*)d_in[12];
    const float* U_w  = (const float*)d_in[13];
    const float* U_b  = (const float*)d_in[14];
    const float* V_w  = (const float*)d_in[15];
    const float* V_b  = (const float*)d_in[16];
    const float* bnhg = (const float*)d_in[17];
    const float* bnhb = (const float*)d_in[18];
    const float* bneg = (const float*)d_in[19];
    const float* bneb = (const float*)d_in[20];
    const float* W1_w = (const float*)d_in[21];
    const float* W1_b = (const float*)d_in[22];
    const float* W2_w = (const float*)d_in[23];
    const float* W2_b = (const float*)d_in[24];
    float* out = (float*)d_out;

    const int n  = in_sizes[0];
    const int ne = in_sizes[1];
    const int* src = eidx;
    const int* dst = eidx + ne;
    const float inv_ne = 1.0f / (float)ne;

    const int TB = 256;
    const int WPB = TB / 32;
    const int G_NODE_W = (n  + WPB - 1) / WPB;
    const int G_EDGE_W = (ne + WPB - 1) / WPB;
    const int G_MMA = 1480;

    // ---- CSR build: 3 launches, no memsets (leave-clean zeroing) ----
    hist_kernel<<<800, TB>>>(dst, ne);                 // #1 (also zeros stats, sync)
    scan_fused<<<SCAN_NB, 1024>>>();                   // #2 (re-zeros hist)
    scatter_kernel<<<800, TB>>>(src, dst, ne);         // #3

    for (int l = 0; l < NL; l++) {
        gemm4_fused<<<G_NODE_W, TB>>>(A_w + l*H*H, A_b + l*H,   // #4 = gemm4(l0)
                                      B_w + l*H*H, B_b + l*H,
                                      U_w + l*H*H, U_b + l*H,
                                      V_w + l*H*H, V_b + l*H,
                                      bnhg + (l-1)*H, bnhb + (l-1)*H,
                                      x, pe_w, pe_b,
                                      l-1, l == 0 ? 0 : 1, n);

        ce_mma<<<G_MMA, 128>>>(C_w + l*H*H, C_b + l*H,          // #5 = ce_mma(l0)
                               bneg + (l-1)*H, bneb + (l-1)*H,
                               ein, ed_w, ed_b,
                               l-1, l == 0 ? 1 : 2, /*writeE=*/1, ne, inv_ne);

        agg2<<<G_NODE_W, TB>>>(l, n);                           // #6 = agg2(l0) <- ncu
    }

    score_gemm2<<<G_NODE_W, TB>>>(W1_w, W1_b,
                                  bnhg + (NL-1)*H, bnhb + (NL-1)*H, NL-1, n);
    // hid_e = e_final @ W1[64:96]; final e-BN fused; no write-back of e
    ce_mma<<<G_MMA, 128>>>(W1_w + 64*32, (const float*)nullptr,
                           bneg + (NL-1)*H, bneb + (NL-1)*H,
                           (const float*)nullptr, (const float*)nullptr,
                           (const float*)nullptr,
                           NL-1, /*eMode=*/2, /*writeE=*/0, ne, inv_ne);
    score_final<<<G_EDGE_W, TB>>>(W2_w, W2_b, out, ne);
}

// round 8
// speedup vs baseline: 1.3274x; 1.0755x over previous
#include <cuda_runtime.h>
#include <cuda_fp16.h>
#include <mma.h>
#include <math.h>

using namespace nvcuda;

#define NN 100000
#define EE 800000
#define H  32
#define NL 4
#define FULL 0xffffffffu
#define SCAN_N   (NN + 1)
#define SCAN_NB  ((SCAN_N + 1023) / 1024)

// ---------------- scratch ---------------------------------------------------------
__device__ float  g_h[NN*H];
__device__ float  g_hnew[NN*H];
__device__ float  g_Ah[NN*H];
__device__ float  g_Bh[NN*H];
__device__ float  g_Uh[NN*H];
__device__ float  g_Vh[NN*H];
__device__ __half g_e[EE*H];       // e_l (dst-sorted)
__device__ __half g_ce[EE*H];      // Ce (fp16 storage, fp32 accum); enew reconstructed
// stats slots: per layer l: [l*128 + 0:64) h sum/sq, [l*128+64:128) e sum/sq
__device__ float  g_stats[NL*128];
__device__ int    g_hist[SCAN_NB*1024];   // zero at load; scan re-zeros (leave-clean)
__device__ int    g_rowptr[NN+1];
__device__ int    g_cursor[NN];
__device__ int    g_bsum[SCAN_NB];
__device__ int    g_sync;
__device__ int    g_ssrc[EE];
__device__ int    g_sdst[EE];
__device__ int    g_oid[EE];

// ---------------- CSR build -------------------------------------------------------
__global__ void hist_kernel(const int* __restrict__ dst, int ne)
{
    if (blockIdx.x == 0) {
        if (threadIdx.x == 0) g_sync = 0;
        for (int i = threadIdx.x; i < NL*128; i += blockDim.x) g_stats[i] = 0.f;
    }
    for (int i = blockIdx.x * blockDim.x + threadIdx.x; i < ne;
         i += gridDim.x * blockDim.x)
        atomicAdd(&g_hist[dst[i]], 1);
}

// single-kernel scan: all SCAN_NB (=98) blocks resident; aggregate + spin barrier.
__global__ void scan_fused()
{
    __shared__ int sm[1024];
    int b = blockIdx.x, t = threadIdx.x;
    int idx = b*1024 + t;
    int v = (idx < SCAN_N) ? g_hist[idx] : 0;
    if (idx < SCAN_N) g_hist[idx] = 0;        // leave clean for next graph replay
    sm[t] = v;
    __syncthreads();
    for (int off = 1; off < 1024; off <<= 1) {
        int u = (t >= off) ? sm[t - off] : 0;
        __syncthreads();
        sm[t] += u;
        __syncthreads();
    }
    if (t == 1023) {
        g_bsum[b] = sm[1023];
        __threadfence();
        atomicAdd(&g_sync, 1);
    }
    if (t == 0) {
        while (atomicAdd(&g_sync, 0) < (int)gridDim.x) __nanosleep(64);
    }
    __syncthreads();
    int pre = 0;
    for (int i = 0; i < b; i++) pre += g_bsum[i];
    int excl = pre + sm[t] - v;
    if (idx < SCAN_N) {
        g_rowptr[idx] = excl;
        if (idx < NN) g_cursor[idx] = excl;
    }
}

__global__ void scatter_kernel(const int* __restrict__ src, const int* __restrict__ dst,
                               int ne)
{
    for (int i = blockIdx.x * blockDim.x + threadIdx.x; i < ne;
         i += gridDim.x * blockDim.x) {
        int d = dst[i];
        int pos = atomicAdd(&g_cursor[d], 1);
        g_ssrc[pos] = src[i];
        g_sdst[pos] = d;
        g_oid[pos]  = i;
    }
}

// ------- gemm4: weights in REGISTERS (zero LDS); grid-stride over rows -----------
// l==0: h = x*pe_w+pe_b inline; l>=1: h += relu(BN(hnew)) inline.
__global__ void __launch_bounds__(128)
gemm4_fused(const float* __restrict__ Aw, const float* __restrict__ Ab,
            const float* __restrict__ Bw, const float* __restrict__ Bb,
            const float* __restrict__ Uw, const float* __restrict__ Ub,
            const float* __restrict__ Vw, const float* __restrict__ Vb,
            const float* __restrict__ bng, const float* __restrict__ bnb,
            const float* __restrict__ x,
            const float* __restrict__ pw, const float* __restrict__ pb,
            int statSlot, int mode /*0=proj,1=update*/, int n)
{
    int lane = threadIdx.x & 31;
    float wA[32], wB[32], wU[32], wV[32];
    #pragma unroll
    for (int k = 0; k < 32; k++) {
        wA[k] = Aw[k*H + lane];
        wB[k] = Bw[k*H + lane];
        wU[k] = Uw[k*H + lane];
        wV[k] = Vw[k*H + lane];
    }
    float bA = Ab[lane], bB = Bb[lane], bU = Ub[lane], bV = Vb[lane];

    float mn = 0.f, sc = 0.f, bt = 0.f, pwl = 0.f, pbl = 0.f;
    if (mode == 1) {
        float inv = 1.0f / (float)n;
        float s1 = g_stats[statSlot*128 + lane];
        float s2 = g_stats[statSlot*128 + 32 + lane];
        mn = s1 * inv;
        float var = s2 * inv - mn * mn;
        sc = rsqrtf(var + 1e-5f) * bng[lane];
        bt = bnb[lane];
    } else {
        pwl = pw[lane]; pbl = pb[lane];
    }

    int warp0  = blockIdx.x * (blockDim.x >> 5) + (threadIdx.x >> 5);
    int stride = gridDim.x * (blockDim.x >> 5);
    for (int row = warp0; row < n; row += stride) {
        float hv;
        if (mode == 0) {
            hv = x[row] * pwl + pbl;
            g_h[row*H + lane] = hv;
        } else {
            hv = g_h[row*H + lane];
            float v = (g_hnew[row*H + lane] - mn) * sc + bt;
            hv += fmaxf(v, 0.f);
            g_h[row*H + lane] = hv;
        }
        float a = bA, b = bB, u = bU, v = bV;
        #pragma unroll
        for (int k = 0; k < 32; k++) {
            float hk = __shfl_sync(FULL, hv, k);
            a += hk * wA[k];
            b += hk * wB[k];
            u += hk * wU[k];
            v += hk * wV[k];
        }
        g_Ah[row*H + lane] = a;
        g_Bh[row*H + lane] = b;
        g_Uh[row*H + lane] = u;
        g_Vh[row*H + lane] = v;
    }
}

// ---- tensor-core edge GEMM -> fp16 ce.
// eMode 1: project e from input (layer 0).
// eMode 2: reconstruct enew_{l-1} = Ah[d]+Bh[s]+ce_prev (gathered, fp32), apply
//          e += relu(BN(enew)); write e back iff writeE. MUST run before gemm4
//          of the next layer (Ah/Bh still hold layer l-1 values), reads/writes
//          g_ce in place (same rows staged then overwritten by this block).
__global__ void ce_mma(const float* __restrict__ W, const float* __restrict__ bias,
                       const float* __restrict__ bng, const float* __restrict__ bnb,
                       const float* __restrict__ ein,
                       const float* __restrict__ ew, const float* __restrict__ eb,
                       int prevSlot, int eMode, int writeE, int ne, float inv_ne)
{
    __shared__ __half sWhi[32*32], sWlo[32*32];
    __shared__ __half sE[4][16*32];
    __shared__ float  sC[4][16*32];
    __shared__ float  sBias[32], sMn[32], sSc[32], sBt[32], sEw[32], sEb[32];

    int tid = threadIdx.x;
    for (int i = tid; i < 1024; i += 128) {
        float w = W[i];
        __half hi = __float2half_rn(w);
        sWhi[i] = hi;
        sWlo[i] = __float2half_rn(w - __half2float(hi));
    }
    if (tid < 32) {
        sBias[tid] = bias ? bias[tid] : 0.f;
        sMn[tid] = 0.f; sSc[tid] = 0.f; sBt[tid] = 0.f;
        sEw[tid] = 0.f; sEb[tid] = 0.f;
        if (eMode == 2) {
            float s1 = g_stats[prevSlot*128 + 64 + tid];
            float s2 = g_stats[prevSlot*128 + 96 + tid];
            float mean = s1 * inv_ne;
            float var  = s2 * inv_ne - mean * mean;
            sMn[tid] = mean;
            sSc[tid] = rsqrtf(var + 1e-5f) * bng[tid];
            sBt[tid] = bnb[tid];
        } else if (eMode == 1) {
            sEw[tid] = ew[tid]; sEb[tid] = eb[tid];
        }
    }
    __syncthreads();

    int warp = tid >> 5, lane = tid & 31;

    wmma::fragment<wmma::matrix_b, 16,16,16, __half, wmma::row_major> bh[2][2], bl[2][2];
    #pragma unroll
    for (int kk = 0; kk < 2; kk++)
        #pragma unroll
        for (int nn = 0; nn < 2; nn++) {
            wmma::load_matrix_sync(bh[kk][nn], sWhi + kk*16*32 + nn*16, 32);
            wmma::load_matrix_sync(bl[kk][nn], sWlo + kk*16*32 + nn*16, 32);
        }

    __half2* e2  = (__half2*)g_e;
    __half2* ce2 = (__half2*)g_ce;
    int ntiles = (ne + 63) >> 6;

    for (int t = blockIdx.x; t < ntiles; t += gridDim.x) {
        int rbase = t*64 + warp*16;
        __half2* stage = (__half2*)sE[warp];
        #pragma unroll
        for (int i = 0; i < 8; i++) {
            int idx = i*32 + lane;
            int row = rbase + (idx >> 4);
            int ch  = idx & 15;
            if (row < ne) {
                size_t g = (size_t)row*16 + ch;
                if (eMode == 1) {
                    float xin = ein[g_oid[row]];
                    int c = ch*2;
                    __half2 nv = __floats2half2_rn(xin*sEw[c] + sEb[c],
                                                   xin*sEw[c+1] + sEb[c+1]);
                    e2[g] = nv;
                    stage[idx] = nv;
                } else {
                    // reconstruct enew_{l-1} and apply BN update
                    int s = g_ssrc[row], d = g_sdst[row];
                    int c = ch*2;
                    float2 ah = *(const float2*)(g_Ah + d*H + c);
                    float2 bhv = *(const float2*)(g_Bh + s*H + c);
                    float2 ce = __half22float2(ce2[g]);
                    float enx = ah.x + bhv.x + ce.x;
                    float eny = ah.y + bhv.y + ce.y;
                    float2 f = __half22float2(e2[g]);
                    f.x += fmaxf((enx - sMn[c])   * sSc[c]   + sBt[c],   0.f);
                    f.y += fmaxf((eny - sMn[c+1]) * sSc[c+1] + sBt[c+1], 0.f);
                    __half2 nv = __floats2half2_rn(f.x, f.y);
                    if (writeE) e2[g] = nv;
                    stage[idx] = nv;
                }
            } else {
                stage[idx] = __floats2half2_rn(0.f, 0.f);
            }
        }
        __syncwarp();

        wmma::fragment<wmma::matrix_a, 16,16,16, __half, wmma::row_major> a0, a1;
        wmma::load_matrix_sync(a0, sE[warp],      32);
        wmma::load_matrix_sync(a1, sE[warp] + 16, 32);

        wmma::fragment<wmma::accumulator, 16,16,16, float> acc0, acc1;
        wmma::fill_fragment(acc0, 0.f);
        wmma::fill_fragment(acc1, 0.f);
        wmma::mma_sync(acc0, a0, bh[0][0], acc0);
        wmma::mma_sync(acc0, a1, bh[1][0], acc0);
        wmma::mma_sync(acc0, a0, bl[0][0], acc0);
        wmma::mma_sync(acc0, a1, bl[1][0], acc0);
        wmma::mma_sync(acc1, a0, bh[0][1], acc1);
        wmma::mma_sync(acc1, a1, bh[1][1], acc1);
        wmma::mma_sync(acc1, a0, bl[0][1], acc1);
        wmma::mma_sync(acc1, a1, bl[1][1], acc1);

        wmma::store_matrix_sync(sC[warp],      acc0, 32, wmma::mem_row_major);
        wmma::store_matrix_sync(sC[warp] + 16, acc1, 32, wmma::mem_row_major);
        __syncwarp();

        #pragma unroll
        for (int r = 0; r < 16; r++) {
            int row = rbase + r;
            if (row < ne)
                g_ce[(size_t)row*32 + lane] =
                    __float2half_rn(sC[warp][r*32 + lane] + sBias[lane]);
        }
        __syncwarp();
    }
}

// ---- aggregation: warp per node; enew computed inline, NOT stored ----------------
__global__ void agg2(int curSlot, int n)
{
    int lane = threadIdx.x & 31;

    __shared__ float sE[32], qE[32], sH[32], qH[32];
    if (threadIdx.x < 32) {
        sE[threadIdx.x] = 0.f; qE[threadIdx.x] = 0.f;
        sH[threadIdx.x] = 0.f; qH[threadIdx.x] = 0.f;
    }
    __syncthreads();

    float ls = 0.f, lq = 0.f, hs = 0.f, hq = 0.f;
    int d = blockIdx.x * (blockDim.x >> 5) + (threadIdx.x >> 5);
    if (d < n) {
        int beg = g_rowptr[d], end = g_rowptr[d+1];
        float ah = g_Ah[d*H + lane];
        float uh = g_Uh[d*H + lane];
        float num = 0.f, den = 0.f;
        int i = beg;
        for (; i + 3 < end; i += 4) {
            int   s[4];
            float ce[4], bh[4], vh[4];
            #pragma unroll
            for (int j = 0; j < 4; j++) s[j] = g_ssrc[i+j];
            #pragma unroll
            for (int j = 0; j < 4; j++) ce[j] = __half2float(g_ce[(size_t)(i+j)*H + lane]);
            #pragma unroll
            for (int j = 0; j < 4; j++) bh[j] = g_Bh[s[j]*H + lane];
            #pragma unroll
            for (int j = 0; j < 4; j++) vh[j] = g_Vh[s[j]*H + lane];
            #pragma unroll
            for (int j = 0; j < 4; j++) {
                float en = ah + bh[j] + ce[j];
                ls += en; lq += en * en;
                float sg = 1.0f / (1.0f + __expf(-en));
                num += sg * vh[j];
                den += sg;
            }
        }
        for (; i < end; i++) {
            int s0 = g_ssrc[i];
            float en = ah + g_Bh[s0*H + lane] + __half2float(g_ce[(size_t)i*H + lane]);
            ls += en; lq += en * en;
            float sg0 = 1.0f / (1.0f + __expf(-en));
            num += sg0 * g_Vh[s0*H + lane];
            den += sg0;
        }
        float hn = uh + num / (den + 1e-6f);
        g_hnew[d*H + lane] = hn;
        hs += hn; hq += hn * hn;
    }
    atomicAdd(&sH[lane], hs); atomicAdd(&qH[lane], hq);
    atomicAdd(&sE[lane], ls); atomicAdd(&qE[lane], lq);
    __syncthreads();
    if (threadIdx.x < 32) {
        atomicAdd(&g_stats[curSlot*128 + threadIdx.x],      sH[threadIdx.x]);
        atomicAdd(&g_stats[curSlot*128 + 32 + threadIdx.x], qH[threadIdx.x]);
        atomicAdd(&g_stats[curSlot*128 + 64 + threadIdx.x], sE[threadIdx.x]);
        atomicAdd(&g_stats[curSlot*128 + 96 + threadIdx.x], qE[threadIdx.x]);
    }
}

// ---- score pre-pass: final h-update fused; hid_src -> g_Ah, hid_dst -> g_Bh ------
// (runs AFTER the final ce_mma, which needs the old Ah/Bh)
__global__ void __launch_bounds__(128)
score_gemm2(const float* __restrict__ W1, const float* __restrict__ b1,
            const float* __restrict__ bng, const float* __restrict__ bnb,
            int statSlot, int n)
{
    int lane = threadIdx.x & 31;
    float ws[32], wd[32];
    #pragma unroll
    for (int k = 0; k < 32; k++) {
        ws[k] = W1[k*32 + lane];
        wd[k] = W1[(32 + k)*32 + lane];
    }
    float bb = b1[lane];
    float inv = 1.0f / (float)n;
    float s1 = g_stats[statSlot*128 + lane];
    float s2 = g_stats[statSlot*128 + 32 + lane];
    float mn = s1 * inv;
    float var = s2 * inv - mn * mn;
    float sc = rsqrtf(var + 1e-5f) * bng[lane];
    float bt = bnb[lane];

    int warp0  = blockIdx.x * (blockDim.x >> 5) + (threadIdx.x >> 5);
    int stride = gridDim.x * (blockDim.x >> 5);
    for (int row = warp0; row < n; row += stride) {
        float hv = g_h[row*H + lane];
        hv += fmaxf((g_hnew[row*H + lane] - mn) * sc + bt, 0.f);
        float a = bb, c = 0.f;
        #pragma unroll
        for (int k = 0; k < 32; k++) {
            float hk = __shfl_sync(FULL, hv, k);
            a += hk * ws[k];
            c += hk * wd[k];
        }
        g_Ah[row*H + lane] = a;
        g_Bh[row*H + lane] = c;
    }
}

// ---- score: hid = relu(hid_s + hid_d + hid_e); out = hid @ W2 + b2 ---------------
__global__ void score_final(const float* __restrict__ W2, const float* __restrict__ b2,
                            float* __restrict__ out, int ne)
{
    int lane = threadIdx.x & 31;
    float w2 = W2[lane];
    float bb2 = b2[0];

    int i = blockIdx.x * (blockDim.x >> 5) + (threadIdx.x >> 5);
    if (i >= ne) return;
    int s = g_ssrc[i], d = g_sdst[i], o = g_oid[i];
    float hid = g_Ah[s*H + lane] + g_Bh[d*H + lane]
              + __half2float(g_ce[(size_t)i*H + lane]);
    hid = fmaxf(hid, 0.f);
    float p = hid * w2;
    #pragma unroll
    for (int off = 16; off > 0; off >>= 1)
        p += __shfl_xor_sync(FULL, p, off);
    if (lane == 0) out[o] = p + bb2;
}

// ==================================================================================
extern "C" void kernel_launch(void* const* d_in, const int* in_sizes, int n_in,
                              void* d_out, int out_size)
{
    const float* x    = (const float*)d_in[0];
    const float* ein  = (const float*)d_in[1];
    const int*   eidx = (const int*)  d_in[2];
    const float* pe_w = (const float*)d_in[3];
    const float* pe_b = (const float*)d_in[4];
    const float* ed_w = (const float*)d_in[5];
    const float* ed_b = (const float*)d_in[6];
    const float* A_w  = (const float*)d_in[7];
    const float* A_b  = (const float*)d_in[8];
    const float* B_w  = (const float*)d_in[9];
    const float* B_b  = (const float*)d_in[10];
    const float* C_w  = (const float*)d_in[11];
    const float* C_b  = (const float*)d_in[12];
    const float* U_w  = (const float*)d_in[13];
    const float* U_b  = (const float*)d_in[14];
    const float* V_w  = (const float*)d_in[15];
    const float* V_b  = (const float*)d_in[16];
    const float* bnhg = (const float*)d_in[17];
    const float* bnhb = (const float*)d_in[18];
    const float* bneg = (const float*)d_in[19];
    const float* bneb = (const float*)d_in[20];
    const float* W1_w = (const float*)d_in[21];
    const float* W1_b = (const float*)d_in[22];
    const float* W2_w = (const float*)d_in[23];
    const float* W2_b = (const float*)d_in[24];
    float* out = (float*)d_out;

    const int n  = in_sizes[0];
    const int ne = in_sizes[1];
    const int* src = eidx;
    const int* dst = eidx + ne;
    const float inv_ne = 1.0f / (float)ne;

    const int TB = 256;
    const int WPB = TB / 32;
    const int G_NODE_W = (n  + WPB - 1) / WPB;
    const int G_EDGE_W = (ne + WPB - 1) / WPB;
    const int G_MMA  = 1480;
    const int G_G4   = 1480;   // grid-stride, 128 threads

    // ---- CSR build ----
    hist_kernel<<<800, TB>>>(dst, ne);                 // #1
    scan_fused<<<SCAN_NB, 1024>>>();                   // #2
    scatter_kernel<<<800, TB>>>(src, dst, ne);         // #3

    for (int l = 0; l < NL; l++) {
        // ce_mma BEFORE gemm4: eMode 2 reconstructs enew_{l-1} from old Ah/Bh.
        ce_mma<<<G_MMA, 128>>>(C_w + l*H*H, C_b + l*H,          // #4 = ce_mma(l0)
                               bneg + (l-1)*H, bneb + (l-1)*H,
                               ein, ed_w, ed_b,
                               l-1, l == 0 ? 1 : 2, /*writeE=*/1, ne, inv_ne);

        gemm4_fused<<<G_G4, 128>>>(A_w + l*H*H, A_b + l*H,      // #5 = gemm4(l0)
                                   B_w + l*H*H, B_b + l*H,
                                   U_w + l*H*H, U_b + l*H,
                                   V_w + l*H*H, V_b + l*H,
                                   bnhg + (l-1)*H, bnhb + (l-1)*H,
                                   x, pe_w, pe_b,
                                   l-1, l == 0 ? 0 : 1, n);

        agg2<<<G_NODE_W, TB>>>(l, n);                           // #6 = agg2(l0) <- ncu
    }

    // final edge term BEFORE score_gemm2 (needs Ah_3/Bh_3 for enew reconstruction)
    ce_mma<<<G_MMA, 128>>>(W1_w + 64*32, (const float*)nullptr,
                           bneg + (NL-1)*H, bneb + (NL-1)*H,
                           (const float*)nullptr, (const float*)nullptr,
                           (const float*)nullptr,
                           NL-1, /*eMode=*/2, /*writeE=*/0, ne, inv_ne);
    score_gemm2<<<G_G4, 128>>>(W1_w, W1_b,
                               bnhg + (NL-1)*H, bnhb + (NL-1)*H, NL-1, n);
    score_final<<<G_EDGE_W, TB>>>(W2_w, W2_b, out, ne);
}